// round 9
// baseline (speedup 1.0000x reference)
#include <cuda_runtime.h>
#include <cstdint>

typedef unsigned long long ull;

__device__ __forceinline__ ull pack2(float x) {
    ull r; asm("mov.b64 %0, {%1, %1};" : "=l"(r) : "f"(x)); return r;
}
__device__ __forceinline__ void ffma2(ull &d, ull a, ull b) {
    asm("fma.rn.f32x2 %0, %1, %2, %0;" : "+l"(d) : "l"(a), "l"(b));
}
__device__ __forceinline__ void unpack2(ull v, float &lo, float &hi) {
    asm("mov.b64 {%0, %1}, %2;" : "=f"(lo), "=f"(hi) : "l"(v));
}
__device__ __forceinline__ uint32_t smem_u32(const void* p) {
    uint32_t a;
    asm("{ .reg .u64 t; cvta.to.shared.u64 t, %1; cvt.u32.u64 %0, t; }"
        : "=r"(a) : "l"(p));
    return a;
}
#define CP_ASYNC16(dst, src) \
    asm volatile("cp.async.cg.shared.global [%0], [%1], 16;" :: "r"(dst), "l"(src))
#define CP_COMMIT()  asm volatile("cp.async.commit_group;" ::: "memory")
#define CP_WAIT(N)   asm volatile("cp.async.wait_group %0;" :: "n"(N) : "memory")
#define BARPAIR(id)  asm volatile("bar.sync %0, 64;" :: "r"(id) : "memory")

// Chunk = 8 u's. Per-node per-chunk row: [x0 8][x1 24][pad 4] = 36 floats
#define ROWF 36
#define BUFF (32 * ROWF)              // one buffer: 32 nodes = 1152 floats
#define NBUF 3
#define XRW  (NBUF * BUFF)            // 3456 floats per 32-node tile
#define WSH  8192                     // weights: 4 x 2048 floats (scaled, h-major)
#define SMEM_FLOATS (WSH + 4 * XRW)   // 8192 + 13824 = 22016
#define SMEM_BYTES  (SMEM_FLOATS * 4) // 88064 (x2 CTAs = 176 KB)

// Warp-pair per 32-node tile. Warp h stages nodes [h*16, h*16+16) and computes
// w-column half h (w in {2h, 2h+1}) for ALL 32 nodes (lane = node index).
// Weight smem layout (scaled by 0.01*C):
//   Wm[u*64 + h*32 + t*8 + v*2 + dw] = c_t * w_t[u, v, 2h+dw]
// -> per u a thread reads 32 contiguous floats = 8 LDS.128, 2 distinct
//    addresses per instruction (one per half-warp... per h across warps:
//    within a warp all lanes share h -> fully uniform broadcast).

__device__ __forceinline__ void stage_half(
    uint32_t xr, const float* __restrict__ nfwarp, int c, int lane, int h)
{
    const int node_lo = lane >> 3, piece = lane & 7;
    const int so  = (piece < 2) ? (8*c + 4*piece) : (128 + 24*c + 4*(piece - 2));
    const int doo = (piece < 2) ? (4*piece)       : (8 + 4*(piece - 2));
    #pragma unroll
    for (int i = 0; i < 4; i++) {
        int node = h*16 + node_lo*4 + i;
        CP_ASYNC16(xr + (uint32_t)(node * ROWF + doo) * 4u,
                   nfwarp + (size_t)node * 512 + so);
    }
}

__global__ void __launch_bounds__(256, 2) fctp_main(
    const float* __restrict__ nf, const float* __restrict__ pf,
    const float* __restrict__ w000, const float* __restrict__ w011,
    const float* __restrict__ w101, const float* __restrict__ w110,
    float* __restrict__ out)
{
    extern __shared__ float S[];
    float* Wm = S;
    const int tid  = threadIdx.x;
    const int warp = tid >> 5, lane = tid & 31;
    const int tile = warp >> 1, h = warp & 1;

    // Stage weights h-major, scaled by 0.01*C
    {
        const float c000 = 3.125e-4f;                // 0.01/32
        const float c110 = 1.8042195912175807e-4f;   // 0.01/(32*sqrt(3))
        for (int i = tid; i < 2048; i += 256) {
            int u = i >> 4, j = i & 15, v = j >> 2, w = j & 3;
            int hh = w >> 1, dw = w & 1;
            int base = u*64 + hh*32 + v*2 + dw;
            Wm[base +  0] = c000 * w000[i];   // t=0
            Wm[base +  8] = c000 * w011[i];   // t=1
            Wm[base + 16] = c110 * w110[i];   // t=2
            Wm[base + 24] = c000 * w101[i];   // t=3
        }
    }
    __syncthreads();

    float* XR = S + WSH + tile * XRW;
    const uint32_t xrb = smem_u32(XR);
    const int nodeBase = blockIdx.x * 128 + tile * 32;
    const float* nfwarp = nf + (size_t)nodeBase * 512;
    const int barid = tile + 1;

    // Accumulators: per v, f32x2 pair (w=2h, w=2h+1). 32 ull = 64 fp32.
    ull z000[4], z011[4], z110[3][4], z101[3][4];
    #pragma unroll
    for (int v = 0; v < 4; v++) {
        z000[v] = 0ull; z011[v] = 0ull;
        z110[0][v] = 0ull; z110[1][v] = 0ull; z110[2][v] = 0ull;
        z101[0][v] = 0ull; z101[1][v] = 0ull; z101[2][v] = 0ull;
    }

    // depth-2 prologue (each warp stages its 16-node half)
    stage_half(xrb,             nfwarp, 0, lane, h);  CP_COMMIT();
    stage_half(xrb + BUFF * 4u, nfwarp, 1, lane, h);  CP_COMMIT();

    for (int c = 0; c < 16; c++) {                    // 16 chunks of 8 u's
        if (c < 14) {
            stage_half(xrb + (uint32_t)(((c + 2) % NBUF) * BUFF) * 4u,
                       nfwarp, c + 2, lane, h);
            CP_COMMIT();
            CP_WAIT(2);                               // my chunk-c group done
        } else if (c == 14) {
            CP_WAIT(1);
        } else {
            CP_WAIT(0);
        }
        BARPAIR(barid);   // both halves of chunk c visible to the pair

        const float* myrow = XR + (c % NBUF) * BUFF + lane * ROWF;
        #pragma unroll
        for (int g = 0; g < 2; g++) {                 // 2 groups of 4 u's
            float4 q0 = *reinterpret_cast<const float4*>(myrow + 4*g);
            float4 qa = *reinterpret_cast<const float4*>(myrow + 8 + 12*g);
            float4 qb = *reinterpret_cast<const float4*>(myrow + 8 + 12*g + 4);
            float4 qc = *reinterpret_cast<const float4*>(myrow + 8 + 12*g + 8);
            float x0s[4] = { q0.x, q0.y, q0.z, q0.w };
            float f1[12] = { qa.x, qa.y, qa.z, qa.w,
                             qb.x, qb.y, qb.z, qb.w,
                             qc.x, qc.y, qc.z, qc.w };
            #pragma unroll
            for (int j = 0; j < 4; j++) {
                const int u = 8*c + 4*g + j;
                const ulonglong2* wp =
                    reinterpret_cast<const ulonglong2*>(Wm + u*64 + h*32);
                ull xa  = pack2(x0s[j]);
                ull xb0 = pack2(f1[3*j + 0]);
                ull xb1 = pack2(f1[3*j + 1]);
                ull xb2 = pack2(f1[3*j + 2]);

                ulonglong2 t0 = wp[0], t0b = wp[1];       // w000: v0v1, v2v3
                ffma2(z000[0], xa, t0.x);  ffma2(z000[1], xa, t0.y);
                ffma2(z000[2], xa, t0b.x); ffma2(z000[3], xa, t0b.y);

                ulonglong2 t1 = wp[2], t1b = wp[3];       // w011
                ffma2(z011[0], xa, t1.x);  ffma2(z011[1], xa, t1.y);
                ffma2(z011[2], xa, t1b.x); ffma2(z011[3], xa, t1b.y);

                ulonglong2 t2 = wp[4], t2b = wp[5];       // w110 (x1 comps)
                ffma2(z110[0][0], xb0, t2.x);  ffma2(z110[0][1], xb0, t2.y);
                ffma2(z110[0][2], xb0, t2b.x); ffma2(z110[0][3], xb0, t2b.y);
                ffma2(z110[1][0], xb1, t2.x);  ffma2(z110[1][1], xb1, t2.y);
                ffma2(z110[1][2], xb1, t2b.x); ffma2(z110[1][3], xb1, t2b.y);
                ffma2(z110[2][0], xb2, t2.x);  ffma2(z110[2][1], xb2, t2.y);
                ffma2(z110[2][2], xb2, t2b.x); ffma2(z110[2][3], xb2, t2b.y);

                ulonglong2 t3 = wp[6], t3b = wp[7];       // w101 (x1 comps)
                ffma2(z101[0][0], xb0, t3.x);  ffma2(z101[0][1], xb0, t3.y);
                ffma2(z101[0][2], xb0, t3b.x); ffma2(z101[0][3], xb0, t3b.y);
                ffma2(z101[1][0], xb1, t3.x);  ffma2(z101[1][1], xb1, t3.y);
                ffma2(z101[1][2], xb1, t3b.x); ffma2(z101[1][3], xb1, t3b.y);
                ffma2(z101[2][0], xb2, t3.x);  ffma2(z101[2][1], xb2, t3.y);
                ffma2(z101[2][2], xb2, t3b.x); ffma2(z101[2][3], xb2, t3b.y);
            }
        }
        BARPAIR(barid);   // pair done reading buffer c%3 before restage
    }

    // ---------------- epilogue (registers only) ----------------
    const int node = nodeBase + lane;

    float f000[4][2], f011[4][2], f110[3][4][2], f101[3][4][2];
    #pragma unroll
    for (int v = 0; v < 4; v++) {
        unpack2(z000[v], f000[v][0], f000[v][1]);
        unpack2(z011[v], f011[v][0], f011[v][1]);
        #pragma unroll
        for (int i = 0; i < 3; i++) {
            unpack2(z110[i][v], f110[i][v][0], f110[i][v][1]);
            unpack2(z101[i][v], f101[i][v][0], f101[i][v][1]);
        }
    }

    float y0v[4], y1v[4][3];
    {
        const float* yp = pf + (size_t)node * 16;
        #pragma unroll
        for (int v = 0; v < 4; v++) {
            y0v[v] = yp[v];
            #pragma unroll
            for (int i = 0; i < 3; i++) y1v[v][i] = yp[4 + 3*v + i];
        }
    }

    float o0[2], o1[2][3];
    #pragma unroll
    for (int ww = 0; ww < 2; ww++) {
        float s = 0.f;
        #pragma unroll
        for (int v = 0; v < 4; v++) {
            s += f000[v][ww] * y0v[v];
            #pragma unroll
            for (int i = 0; i < 3; i++)
                s += f110[i][v][ww] * y1v[v][i];
        }
        o0[ww] = s;
        #pragma unroll
        for (int k = 0; k < 3; k++) {
            float t = 0.f;
            #pragma unroll
            for (int v = 0; v < 4; v++)
                t += f011[v][ww] * y1v[v][k] + f101[k][v][ww] * y0v[v];
            o1[ww][k] = t;
        }
    }
    if (h == 0) o0[0] = 0.0f;   // reference zeroes out[:,0]

    float* op = out + (size_t)node * 16;
    op[2*h    ] = o0[0];
    op[2*h + 1] = o0[1];
    float* o1p = op + 4 + 6*h;   // h=0 -> floats 4..9 (w=0,1); h=1 -> 10..15
    o1p[0] = o1[0][0]; o1p[1] = o1[0][1]; o1p[2] = o1[0][2];
    o1p[3] = o1[1][0]; o1p[4] = o1[1][1]; o1p[5] = o1[1][2];
}

// naive tail kernel (only runs if n % 128 != 0; negligible work)
__global__ void fctp_tail(
    const float* __restrict__ nf, const float* __restrict__ pf,
    const float* __restrict__ w000, const float* __restrict__ w011,
    const float* __restrict__ w101, const float* __restrict__ w110,
    float* __restrict__ out, int start, int n)
{
    int node = start + blockIdx.x * blockDim.x + threadIdx.x;
    if (node >= n) return;
    const float* x = nf + (size_t)node * 512;
    const float* y = pf + (size_t)node * 16;
    float y0v[4], y1v[4][3];
    for (int v0 = 0; v0 < 4; v0++) {
        y0v[v0] = y[v0];
        for (int i = 0; i < 3; i++) y1v[v0][i] = y[4 + 3*v0 + i];
    }
    float o0[4] = {0,0,0,0}, o1[4][3] = {};
    for (int u = 0; u < 128; u++) {
        float x0u = x[u];
        float x1u[3] = { x[128 + 3*u], x[128 + 3*u + 1], x[128 + 3*u + 2] };
        for (int v0 = 0; v0 < 4; v0++) {
            float s110 = x1u[0]*y1v[v0][0] + x1u[1]*y1v[v0][1] + x1u[2]*y1v[v0][2];
            float xy0 = x0u * y0v[v0];
            for (int w = 0; w < 4; w++) {
                int idx = u*16 + v0*4 + w;
                o0[w] += 3.125e-4f * xy0 * w000[idx]
                       + 1.8042195912175807e-4f * s110 * w110[idx];
                for (int k = 0; k < 3; k++)
                    o1[w][k] += 3.125e-4f * (x0u * y1v[v0][k] * w011[idx]
                                           + x1u[k] * y0v[v0] * w101[idx]);
            }
        }
    }
    o0[0] = 0.0f;
    float* op = out + (size_t)node * 16;
    for (int w = 0; w < 4; w++) op[w] = o0[w];
    for (int w = 0; w < 4; w++)
        for (int k = 0; k < 3; k++) op[4 + 3*w + k] = o1[w][k];
}

extern "C" void kernel_launch(void* const* d_in, const int* in_sizes, int n_in,
                              void* d_out, int out_size) {
    const float* nf   = (const float*)d_in[0];
    const float* pf   = (const float*)d_in[1];
    const float* w000 = (const float*)d_in[2];
    const float* w011 = (const float*)d_in[3];
    const float* w101 = (const float*)d_in[4];
    const float* w110 = (const float*)d_in[5];
    float* out = (float*)d_out;
    int n = in_sizes[0] / 512;
    int nb  = n >> 7;
    int rem = n & 127;
    cudaFuncSetAttribute(fctp_main, cudaFuncAttributeMaxDynamicSharedMemorySize, SMEM_BYTES);
    if (nb > 0)
        fctp_main<<<nb, 256, SMEM_BYTES>>>(nf, pf, w000, w011, w101, w110, out);
    if (rem > 0)
        fctp_tail<<<1, 128>>>(nf, pf, w000, w011, w101, w110, out, nb * 128, n);
}